// round 14
// baseline (speedup 1.0000x reference)
#include <cuda_runtime.h>
#include <cuda_fp16.h>
#include <cstdint>

// FlashAttention via warp-level mma.sync (HMMA), sm_103 baseline target.
// B=2, S=2048, H=16, D=64, fp32 I/O.
// Round 14: full double-buffering (K,V,bias) -> ONE cp.async group and ONE
//           __syncthreads per tile. fp16 operands, fp32 accumulate.

#define S_LEN 2048
#define H_NUM 16
#define MT    128
#define NT    64
#define SCALEF 0.125f

// dynamic smem offsets (bytes from 1024-aligned base); 128B rows, SW128
#define OFF_Q    0            // 128 x 64 fp16 = 16KB
#define OFF_K0   16384        // 8KB
#define OFF_K1   24576
#define OFF_V0   32768        // 8KB
#define OFF_V1   40960
#define OFF_B0   49152        // 32KB (128 rows x 256B fp32, xor-16B swizzled)
#define OFF_B1   81920
#define DSMEM_BYTES (114688 + 1024)   // 113 KB -> 2 CTAs/SM (226.5 KB < 228 KB)

// pre-converted K/V planes: [arr][b][h][s][d]; arr: 0=K 1=V
#define KV_PLANE (2u * H_NUM * S_LEN * 64u)
__device__ __half g_kv[2][2][H_NUM][S_LEN][64];

static __device__ __forceinline__ uint32_t swz(uint32_t o){ return o ^ ((o >> 3) & 0x70u); }

static __device__ __forceinline__ uint32_t smem_u32(const void* p){
    uint32_t a;
    asm("{ .reg .u64 t; cvta.to.shared.u64 t, %1; cvt.u32.u64 %0, t; }" : "=r"(a) : "l"(p));
    return a;
}

#define LDSM_X4(r, addr) \
    asm volatile("ldmatrix.sync.aligned.m8n8.x4.shared.b16 {%0,%1,%2,%3}, [%4];" \
        : "=r"((r)[0]), "=r"((r)[1]), "=r"((r)[2]), "=r"((r)[3]) : "r"(addr))

#define LDSM_X4T(r, addr) \
    asm volatile("ldmatrix.sync.aligned.m8n8.x4.trans.shared.b16 {%0,%1,%2,%3}, [%4];" \
        : "=r"((r)[0]), "=r"((r)[1]), "=r"((r)[2]), "=r"((r)[3]) : "r"(addr))

#define MMA(d, a, b0, b1) \
    asm volatile("mma.sync.aligned.m16n8k16.row.col.f32.f16.f16.f32 " \
        "{%0,%1,%2,%3},{%4,%5,%6,%7},{%8,%9},{%0,%1,%2,%3};" \
        : "+f"((d)[0]), "+f"((d)[1]), "+f"((d)[2]), "+f"((d)[3]) \
        : "r"((a)[0]), "r"((a)[1]), "r"((a)[2]), "r"((a)[3]), "r"(b0), "r"(b1))

#define CP16(smem, gmem) \
    asm volatile("cp.async.cg.shared.global [%0], [%1], 16;" :: "r"(smem), "l"(gmem))
#define CP_COMMIT() asm volatile("cp.async.commit_group;" ::: "memory")
#define CP_WAIT0()  asm volatile("cp.async.wait_group 0;"  ::: "memory")

static __device__ __forceinline__ uint32_t pk2h(float a, float b){
    uint32_t r;
    asm("cvt.rn.f16x2.f32 %0, %1, %2;" : "=r"(r) : "f"(b), "f"(a));
    return r;
}

// ---------------- pre-pass: K,V (fp32) -> fp16 planes ----------------
// Index space: 2^21 threads -> (b, s, kv, h, d4). Launch <<<8192, 256>>>.
__global__ void __launch_bounds__(256)
convert_kv_kernel(const float* __restrict__ qkv)
{
    const int idx = blockIdx.x * 256 + threadIdx.x;
    const int d4 = idx & 15;
    const int h  = (idx >> 4) & 15;
    const int kv = (idx >> 8) & 1;
    const int s  = (idx >> 9) & 2047;
    const int b  = idx >> 20;

    const float4 v = *(const float4*)(qkv
        + ((size_t)(b * 2048 + s) * 3 + 1 + kv) * 1024 + h * 64 + d4 * 4);
    uint32_t h0 = pk2h(v.x, v.y);
    uint32_t h1 = pk2h(v.z, v.w);
    *(uint2*)&g_kv[kv][b][h][s][d4 * 4] = make_uint2(h0, h1);
}

extern __shared__ char dynsm[];

__global__ void __launch_bounds__(256, 2)
fa_mma_kernel(const float* __restrict__ qkv, const float* __restrict__ pb,
              float* __restrict__ out)
{
    const int mi  = (int)(gridDim.x - 1u) - (int)blockIdx.x;
    const int h   = blockIdx.y;
    const int b   = blockIdx.z;
    const int tid = threadIdx.x;
    const int w   = tid >> 5;
    const int l   = tid & 31;
    const int qr  = l >> 2;
    const int qc  = l & 3;
    const int m0  = mi * MT;
    const int mg0 = m0 + w * 16 + qr;
    const int mg1 = mg0 + 8;
    const int wrow_max = m0 + w * 16 + 15;

    const uint32_t sbase = (smem_u32(dynsm) + 1023u) & ~1023u;
    const uint32_t sQ = sbase + OFF_Q;

    const float* qhd = qkv + (size_t)b * S_LEN * 3072 + (size_t)h * 64;
    const float* pbh = pb + (size_t)h * S_LEN * S_LEN;

    const int st_n = tid >> 4;
    const int st_g = tid & 15;

    // K/V cp.async mapping: thread -> row n (0..63), two 16B chunks
    const int kn  = tid >> 2;
    const int kc0 = (tid & 3) * 2;
    const uint32_t kd0 = swz((uint32_t)(kn * 128 + kc0 * 16));
    const uint32_t kd1 = swz((uint32_t)(kn * 128 + (kc0 + 1) * 16));
    const __half* kvbase = &g_kv[0][b][h][0][0];
    const size_t kv_row_off = (size_t)kn * 64 + kc0 * 8;

    // bias staging
    const float* bias_src0 = pbh + (size_t)(m0 + st_n) * S_LEN + st_g * 4;
    const uint32_t bias_off = (uint32_t)st_n * 256 + ((uint32_t)(st_g ^ (st_n & 15)) << 4);

    const int nt = 2 * (mi + 1);

    // ---- prologue: issue full group(0) (K,V,bias into buffer 0) ----
    {
        const __half* src = kvbase + kv_row_off;
        CP16(sbase + OFF_K0 + kd0, src);              CP16(sbase + OFF_K0 + kd1, src + 8);
        CP16(sbase + OFF_V0 + kd0, src + KV_PLANE);   CP16(sbase + OFF_V0 + kd1, src + KV_PLANE + 8);
        #pragma unroll
        for (int r = 0; r < 8; r++)
            CP16(sbase + OFF_B0 + bias_off + (uint32_t)r * 4096,
                 bias_src0 + (size_t)r * 16 * S_LEN);
        CP_COMMIT();   // group(0)
    }

    // ---- stage Q (fp16, SW128) while tile-0 copies fly ----
    #pragma unroll
    for (int r = 0; r < 8; r++) {
        int idx = tid + r * 256;
        int m = idx >> 4, g = idx & 15;
        float4 v = *(const float4*)(qhd + (size_t)(m0 + m) * 3072 + g * 4);
        uint32_t o = swz((uint32_t)(m * 128 + g * 8));
        uint32_t h0 = pk2h(v.x, v.y), h1 = pk2h(v.z, v.w);
        asm volatile("st.shared.v2.u32 [%0], {%1,%2};" :: "r"(sQ + o), "r"(h0), "r"(h1));
    }

    float O[8][4];
    #pragma unroll
    for (int i = 0; i < 8; i++)
        #pragma unroll
        for (int j = 0; j < 4; j++) O[i][j] = 0.f;
    float lsum0 = 0.f, lsum1 = 0.f;

    const int r0loc = w * 16 + qr;
    const uint32_t bq = (uint32_t)(qc & 1) * 8;
    const int gq = qc >> 1;

    for (int t = 0; t < nt; t++) {
        const int n0 = t * NT;
        const bool active = (n0 <= wrow_max);
        const bool haveNext = (t + 1 < nt);
        const uint32_t sK = sbase + ((t & 1) ? OFF_K1 : OFF_K0);
        const uint32_t sV = sbase + ((t & 1) ? OFF_V1 : OFF_V0);
        const uint32_t sB = sbase + ((t & 1) ? OFF_B1 : OFF_B0);
        const uint32_t sKa = sbase + ((t & 1) ? OFF_K0 : OFF_K1);
        const uint32_t sVa = sbase + ((t & 1) ? OFF_V0 : OFF_V1);
        const uint32_t sBa = sbase + ((t & 1) ? OFF_B0 : OFF_B1);

        // ---- THE one wait + one barrier per tile ----
        CP_WAIT0();          // group(t) landed (issued one full tile ago)
        __syncthreads();     // all warps done reading tile t-1 buffers; t visible

        // ---- issue group(t+1) into the alternate buffers (read by t-1, now free) ----
        if (haveNext) {
            const int n1 = n0 + NT;
            const __half* src = kvbase + (size_t)n1 * 64 + kv_row_off;
            CP16(sKa + kd0, src);              CP16(sKa + kd1, src + 8);
            CP16(sVa + kd0, src + KV_PLANE);   CP16(sVa + kd1, src + KV_PLANE + 8);
            const float* gsrc = bias_src0 + n1;
            #pragma unroll
            for (int r = 0; r < 8; r++)
                CP16(sBa + bias_off + (uint32_t)r * 4096, gsrc + (size_t)r * 16 * S_LEN);
        }
        CP_COMMIT();   // group(t+1) (empty on last tile keeps counts aligned)

        if (!active) continue;

        // ---- S = Q K^T : fp16 x fp16 -> fp32 ----
        float S[8][4];
        #pragma unroll
        for (int i = 0; i < 8; i++)
            #pragma unroll
            for (int j = 0; j < 4; j++) S[i][j] = 0.f;

        #pragma unroll
        for (int kt = 0; kt < 4; kt++) {
            uint32_t qh[4];
            uint32_t qoff = swz((uint32_t)((w * 16 + ((l >> 3) & 1) * 8 + (l & 7)) * 128
                                           + kt * 32 + (l >> 4) * 16));
            LDSM_X4(qh, sQ + qoff);
            #pragma unroll
            for (int np = 0; np < 4; np++) {
                uint32_t kh[4];
                uint32_t koff = swz((uint32_t)((np * 16 + ((l >> 4) & 1) * 8 + (l & 7)) * 128
                                               + kt * 32 + ((l >> 3) & 1) * 16));
                LDSM_X4(kh, sK + koff);
                MMA(S[2*np],   qh, kh[0], kh[1]);
                MMA(S[2*np+1], qh, kh[2], kh[3]);
            }
        }

        // ---- epilogue + O += P V, interleaved per k16 group ----
        const bool needmask = (n0 + 63 > m0 + w * 16);
        #pragma unroll
        for (int kp = 0; kp < 4; kp++) {
            uint32_t ph[4];
            #pragma unroll
            for (int jj = 0; jj < 2; jj++) {
                const int j = 2 * kp + jj;
                const int g16 = 2 * j + gq;
                const uint32_t a0 = sB + (uint32_t)r0loc * 256
                                    + ((uint32_t)(g16 ^ (r0loc & 15)) << 4) + bq;
                const uint32_t a1 = sB + (uint32_t)(r0loc + 8) * 256
                                    + ((uint32_t)(g16 ^ ((r0loc + 8) & 15)) << 4) + bq;
                float b0x, b0y, b1x, b1y;
                asm volatile("ld.shared.v2.f32 {%0,%1}, [%2];" : "=f"(b0x), "=f"(b0y) : "r"(a0));
                asm volatile("ld.shared.v2.f32 {%0,%1}, [%2];" : "=f"(b1x), "=f"(b1y) : "r"(a1));
                const int col = n0 + 8 * j + 2 * qc;
                float p00 = __expf(fmaf(S[j][0], SCALEF, b0x));
                float p01 = __expf(fmaf(S[j][1], SCALEF, b0y));
                float p10 = __expf(fmaf(S[j][2], SCALEF, b1x));
                float p11 = __expf(fmaf(S[j][3], SCALEF, b1y));
                if (needmask) {
                    if (col     > mg0) p00 = 0.f;
                    if (col + 1 > mg0) p01 = 0.f;
                    if (col     > mg1) p10 = 0.f;
                    if (col + 1 > mg1) p11 = 0.f;
                }
                lsum0 += p00 + p01;
                lsum1 += p10 + p11;
                ph[jj*2]     = pk2h(p00, p01);
                ph[jj*2 + 1] = pk2h(p10, p11);
            }
            #pragma unroll
            for (int dp = 0; dp < 4; dp++) {
                uint32_t vh[4];
                uint32_t voff = swz((uint32_t)((kp * 16 + ((l >> 3) & 1) * 8 + (l & 7)) * 128
                                               + dp * 32 + ((l >> 4) & 1) * 16));
                LDSM_X4T(vh, sV + voff);
                MMA(O[2*dp],   ph, vh[0], vh[1]);
                MMA(O[2*dp+1], ph, vh[2], vh[3]);
            }
        }
    }

    // ---- normalize and store ----
    lsum0 += __shfl_xor_sync(0xffffffffu, lsum0, 1);
    lsum0 += __shfl_xor_sync(0xffffffffu, lsum0, 2);
    lsum1 += __shfl_xor_sync(0xffffffffu, lsum1, 1);
    lsum1 += __shfl_xor_sync(0xffffffffu, lsum1, 2);
    const float inv0 = 1.f / lsum0;
    const float inv1 = 1.f / lsum1;

    float* o0 = out + (((size_t)b * S_LEN + mg0) * H_NUM + h) * 64 + 2 * qc;
    float* o1 = out + (((size_t)b * S_LEN + mg1) * H_NUM + h) * 64 + 2 * qc;
    #pragma unroll
    for (int dn = 0; dn < 8; dn++) {
        float2 r0v = make_float2(O[dn][0] * inv0, O[dn][1] * inv0);
        float2 r1v = make_float2(O[dn][2] * inv1, O[dn][3] * inv1);
        *(float2*)(o0 + 8 * dn) = r0v;
        *(float2*)(o1 + 8 * dn) = r1v;
    }
}

extern "C" void kernel_launch(void* const* d_in, const int* in_sizes, int n_in,
                              void* d_out, int out_size)
{
    const float* qkv = (const float*)d_in[0];
    const float* pb  = (const float*)d_in[1];
    float* out       = (float*)d_out;

    convert_kv_kernel<<<8192, 256>>>(qkv);   // 2^21 threads: full (b,s,kv,h,d4) space

    cudaFuncSetAttribute(fa_mma_kernel, cudaFuncAttributeMaxDynamicSharedMemorySize, DSMEM_BYTES);
    dim3 grid(S_LEN / MT, H_NUM, 2);
    fa_mma_kernel<<<grid, 256, DSMEM_BYTES>>>(qkv, pb, out);
}

// round 15
// speedup vs baseline: 1.0103x; 1.0103x over previous
#include <cuda_runtime.h>
#include <cuda_fp16.h>
#include <cstdint>

// FlashAttention via warp-level mma.sync (HMMA), sm_103 baseline target.
// B=2, S=2048, H=16, D=64, fp32 I/O.
// Round 15: R13 staging + register diet: Q fragments cached in regs (tile-
//           invariant), S halved (process two column-halves per tile with
//           QK -> epilogue -> PV fused per half). Frees ~20 regs of
//           scheduling headroom at the former 128-reg wall.

#define S_LEN 2048
#define H_NUM 16
#define MT    128
#define NT    64
#define SCALEF 0.125f

// dynamic smem offsets (bytes from 1024-aligned base); 128B rows, SW128
#define OFF_QHI  0            // 128 x 64 fp16 = 16KB
#define OFF_K0   16384        // stage 0: K (8KB)
#define OFF_K1   24576        // stage 1
#define OFF_VHI  32768        // 8KB
#define OFF_BIAS 40960        // 128 rows x 256B fp32 = 32KB (xor-16B swizzled)
#define DSMEM_BYTES (73728 + 1024)

// pre-converted K/V planes: [arr][b][h][s][d]; arr: 0=K 1=V
#define KV_PLANE (2u * H_NUM * S_LEN * 64u)
__device__ __half g_kv[2][2][H_NUM][S_LEN][64];

static __device__ __forceinline__ uint32_t swz(uint32_t o){ return o ^ ((o >> 3) & 0x70u); }

static __device__ __forceinline__ uint32_t smem_u32(const void* p){
    uint32_t a;
    asm("{ .reg .u64 t; cvta.to.shared.u64 t, %1; cvt.u32.u64 %0, t; }" : "=r"(a) : "l"(p));
    return a;
}

#define LDSM_X4(r, addr) \
    asm volatile("ldmatrix.sync.aligned.m8n8.x4.shared.b16 {%0,%1,%2,%3}, [%4];" \
        : "=r"((r)[0]), "=r"((r)[1]), "=r"((r)[2]), "=r"((r)[3]) : "r"(addr))

#define LDSM_X4T(r, addr) \
    asm volatile("ldmatrix.sync.aligned.m8n8.x4.trans.shared.b16 {%0,%1,%2,%3}, [%4];" \
        : "=r"((r)[0]), "=r"((r)[1]), "=r"((r)[2]), "=r"((r)[3]) : "r"(addr))

#define MMA(d, a, b0, b1) \
    asm volatile("mma.sync.aligned.m16n8k16.row.col.f32.f16.f16.f32 " \
        "{%0,%1,%2,%3},{%4,%5,%6,%7},{%8,%9},{%0,%1,%2,%3};" \
        : "+f"((d)[0]), "+f"((d)[1]), "+f"((d)[2]), "+f"((d)[3]) \
        : "r"((a)[0]), "r"((a)[1]), "r"((a)[2]), "r"((a)[3]), "r"(b0), "r"(b1))

#define CP16(smem, gmem) \
    asm volatile("cp.async.cg.shared.global [%0], [%1], 16;" :: "r"(smem), "l"(gmem))
#define CP_COMMIT() asm volatile("cp.async.commit_group;" ::: "memory")
#define CP_WAIT0()  asm volatile("cp.async.wait_group 0;"  ::: "memory")
#define CP_WAIT1()  asm volatile("cp.async.wait_group 1;"  ::: "memory")

static __device__ __forceinline__ uint32_t pk2h(float a, float b){
    uint32_t r;
    asm("cvt.rn.f16x2.f32 %0, %1, %2;" : "=r"(r) : "f"(b), "f"(a));
    return r;
}

// ---------------- pre-pass: K,V (fp32) -> fp16 planes ----------------
// Index space: 2^21 threads -> (b, s, kv, h, d4). Launch <<<8192, 256>>>.
__global__ void __launch_bounds__(256)
convert_kv_kernel(const float* __restrict__ qkv)
{
    const int idx = blockIdx.x * 256 + threadIdx.x;
    const int d4 = idx & 15;
    const int h  = (idx >> 4) & 15;
    const int kv = (idx >> 8) & 1;
    const int s  = (idx >> 9) & 2047;
    const int b  = idx >> 20;

    const float4 v = *(const float4*)(qkv
        + ((size_t)(b * 2048 + s) * 3 + 1 + kv) * 1024 + h * 64 + d4 * 4);
    uint32_t h0 = pk2h(v.x, v.y);
    uint32_t h1 = pk2h(v.z, v.w);
    *(uint2*)&g_kv[kv][b][h][s][d4 * 4] = make_uint2(h0, h1);
}

extern __shared__ char dynsm[];

__global__ void __launch_bounds__(256, 2)
fa_mma_kernel(const float* __restrict__ qkv, const float* __restrict__ pb,
              float* __restrict__ out)
{
    const int mi  = (int)(gridDim.x - 1u) - (int)blockIdx.x;
    const int h   = blockIdx.y;
    const int b   = blockIdx.z;
    const int tid = threadIdx.x;
    const int w   = tid >> 5;
    const int l   = tid & 31;
    const int qr  = l >> 2;
    const int qc  = l & 3;
    const int m0  = mi * MT;
    const int mg0 = m0 + w * 16 + qr;
    const int mg1 = mg0 + 8;
    const int wrow_max = m0 + w * 16 + 15;

    const uint32_t sbase = (smem_u32(dynsm) + 1023u) & ~1023u;
    const uint32_t sQ = sbase + OFF_QHI;
    const uint32_t sV = sbase + OFF_VHI;
    const uint32_t sB = sbase + OFF_BIAS;

    const float* qhd = qkv + (size_t)b * S_LEN * 3072 + (size_t)h * 64;
    const float* pbh = pb + (size_t)h * S_LEN * S_LEN;

    const int st_n = tid >> 4;
    const int st_g = tid & 15;

    // K/V cp.async mapping: thread -> row n (0..63), two 16B chunks
    const int kn  = tid >> 2;
    const int kc0 = (tid & 3) * 2;
    const uint32_t kd0 = swz((uint32_t)(kn * 128 + kc0 * 16));
    const uint32_t kd1 = swz((uint32_t)(kn * 128 + (kc0 + 1) * 16));
    const __half* kvbase = &g_kv[0][b][h][0][0];
    const size_t kv_row_off = (size_t)kn * 64 + kc0 * 8;

    // bias staging
    const float* bias_src0 = pbh + (size_t)(m0 + st_n) * S_LEN + st_g * 4;
    const uint32_t bias_dst = sB + (uint32_t)st_n * 256 + ((uint32_t)(st_g ^ (st_n & 15)) << 4);

    const int nt = 2 * (mi + 1);

    // ---- prologue: group {K(0)}, then group {bias(0), V(0)} ----
    {
        const __half* src = kvbase + kv_row_off;
        const uint32_t k0 = sbase + OFF_K0;
        CP16(k0 + kd0, src);                       CP16(k0 + kd1, src + 8);
        CP_COMMIT();   // K(0)
        #pragma unroll
        for (int r = 0; r < 8; r++)
            CP16(bias_dst + (uint32_t)r * 4096, bias_src0 + (size_t)r * 16 * S_LEN);
        CP16(sV + kd0, src + KV_PLANE);            CP16(sV + kd1, src + KV_PLANE + 8);
        CP_COMMIT();   // biasV(0)
    }

    // ---- stage Q (fp16, SW128) while tile-0 copies fly ----
    #pragma unroll
    for (int r = 0; r < 8; r++) {
        int idx = tid + r * 256;
        int m = idx >> 4, g = idx & 15;
        float4 v = *(const float4*)(qhd + (size_t)(m0 + m) * 3072 + g * 4);
        uint32_t o = swz((uint32_t)(m * 128 + g * 8));
        uint32_t h0 = pk2h(v.x, v.y), h1 = pk2h(v.z, v.w);
        asm volatile("st.shared.v2.u32 [%0], {%1,%2};" :: "r"(sQ + o), "r"(h0), "r"(h1));
    }
    __syncthreads();   // Q visible

    // ---- cache Q fragments in registers (tile-invariant) ----
    uint32_t qcf[4][4];
    #pragma unroll
    for (int kt = 0; kt < 4; kt++) {
        uint32_t qoff = swz((uint32_t)((w * 16 + ((l >> 3) & 1) * 8 + (l & 7)) * 128
                                       + kt * 32 + (l >> 4) * 16));
        LDSM_X4(qcf[kt], sQ + qoff);
    }

    float O[8][4];
    #pragma unroll
    for (int i = 0; i < 8; i++)
        #pragma unroll
        for (int j = 0; j < 4; j++) O[i][j] = 0.f;
    float lsum0 = 0.f, lsum1 = 0.f;

    const int r0loc = w * 16 + qr;
    const uint32_t bq = (uint32_t)(qc & 1) * 8;
    const int gq = qc >> 1;

    for (int t = 0; t < nt; t++) {
        const int n0 = t * NT;
        const bool active = (n0 <= wrow_max);
        const bool haveNext = (t + 1 < nt);
        const uint32_t sK  = sbase + ((t & 1) ? OFF_K1 : OFF_K0);
        const uint32_t sKn = sbase + ((t & 1) ? OFF_K0 : OFF_K1);
        const bool needmask = (n0 + 63 > m0 + w * 16);

        // ---- wait K(t) (issued one phase ago; biasV(t) may still fly) ----
        CP_WAIT1();
        __syncthreads();

        #pragma unroll
        for (int half = 0; half < 2; half++) {
            // ---- QK for this column-half: S uses only 16 regs ----
            float S[4][4];
            if (active) {
                #pragma unroll
                for (int i = 0; i < 4; i++)
                    #pragma unroll
                    for (int j = 0; j < 4; j++) S[i][j] = 0.f;

                #pragma unroll
                for (int kt = 0; kt < 4; kt++) {
                    #pragma unroll
                    for (int i2 = 0; i2 < 2; i2++) {
                        const int np = half * 2 + i2;
                        uint32_t kh[4];
                        uint32_t koff = swz((uint32_t)((np * 16 + ((l >> 4) & 1) * 8 + (l & 7)) * 128
                                                       + kt * 32 + ((l >> 3) & 1) * 16));
                        LDSM_X4(kh, sK + koff);
                        MMA(S[2*i2],   qcf[kt], kh[0], kh[1]);
                        MMA(S[2*i2+1], qcf[kt], kh[2], kh[3]);
                    }
                }
            }

            // ---- between halves: wait biasV(t) (hidden under half-0 QK),
            //      then issue K(t+1) into the freed alternate buffer ----
            if (half == 0) {
                CP_WAIT0();
                __syncthreads();
                if (haveNext) {
                    const __half* src = kvbase + (size_t)(n0 + NT) * 64 + kv_row_off;
                    CP16(sKn + kd0, src);  CP16(sKn + kd1, src + 8);
                }
                CP_COMMIT();   // K(t+1) (empty group on last tile keeps counts aligned)
            }

            // ---- epilogue + O += P V for this half ----
            if (active) {
                #pragma unroll
                for (int i2 = 0; i2 < 2; i2++) {
                    const int kp = half * 2 + i2;
                    uint32_t ph[4];
                    #pragma unroll
                    for (int jj = 0; jj < 2; jj++) {
                        const int j = 2 * kp + jj;        // global column block
                        const float* Sl = S[2*i2 + jj];
                        const int g16 = 2 * j + gq;
                        const uint32_t a0 = sB + (uint32_t)r0loc * 256
                                            + ((uint32_t)(g16 ^ (r0loc & 15)) << 4) + bq;
                        const uint32_t a1 = sB + (uint32_t)(r0loc + 8) * 256
                                            + ((uint32_t)(g16 ^ ((r0loc + 8) & 15)) << 4) + bq;
                        float b0x, b0y, b1x, b1y;
                        asm volatile("ld.shared.v2.f32 {%0,%1}, [%2];" : "=f"(b0x), "=f"(b0y) : "r"(a0));
                        asm volatile("ld.shared.v2.f32 {%0,%1}, [%2];" : "=f"(b1x), "=f"(b1y) : "r"(a1));
                        const int col = n0 + 8 * j + 2 * qc;
                        float p00 = __expf(fmaf(Sl[0], SCALEF, b0x));
                        float p01 = __expf(fmaf(Sl[1], SCALEF, b0y));
                        float p10 = __expf(fmaf(Sl[2], SCALEF, b1x));
                        float p11 = __expf(fmaf(Sl[3], SCALEF, b1y));
                        if (needmask) {
                            if (col     > mg0) p00 = 0.f;
                            if (col + 1 > mg0) p01 = 0.f;
                            if (col     > mg1) p10 = 0.f;
                            if (col + 1 > mg1) p11 = 0.f;
                        }
                        lsum0 += p00 + p01;
                        lsum1 += p10 + p11;
                        ph[jj*2]     = pk2h(p00, p01);
                        ph[jj*2 + 1] = pk2h(p10, p11);
                    }
                    #pragma unroll
                    for (int dp = 0; dp < 4; dp++) {
                        uint32_t vh[4];
                        uint32_t voff = swz((uint32_t)((kp * 16 + ((l >> 3) & 1) * 8 + (l & 7)) * 128
                                                       + dp * 32 + ((l >> 4) & 1) * 16));
                        LDSM_X4T(vh, sV + voff);
                        MMA(O[2*dp],   ph, vh[0], vh[1]);
                        MMA(O[2*dp+1], ph, vh[2], vh[3]);
                    }
                }
            }
        }

        __syncthreads();   // bias/V reads done by all -> buffers free

        // ---- issue group {bias(t+1), V(t+1)} ----
        if (haveNext) {
            const int n1 = n0 + NT;
            const float* gsrc = bias_src0 + n1;
            #pragma unroll
            for (int r = 0; r < 8; r++)
                CP16(bias_dst + (uint32_t)r * 4096, gsrc + (size_t)r * 16 * S_LEN);
            const __half* src = kvbase + (size_t)n1 * 64 + kv_row_off;
            CP16(sV + kd0, src + KV_PLANE);  CP16(sV + kd1, src + KV_PLANE + 8);
        }
        CP_COMMIT();   // biasV(t+1)
    }

    // ---- normalize and store ----
    lsum0 += __shfl_xor_sync(0xffffffffu, lsum0, 1);
    lsum0 += __shfl_xor_sync(0xffffffffu, lsum0, 2);
    lsum1 += __shfl_xor_sync(0xffffffffu, lsum1, 1);
    lsum1 += __shfl_xor_sync(0xffffffffu, lsum1, 2);
    const float inv0 = 1.f / lsum0;
    const float inv1 = 1.f / lsum1;

    float* o0 = out + (((size_t)b * S_LEN + mg0) * H_NUM + h) * 64 + 2 * qc;
    float* o1 = out + (((size_t)b * S_LEN + mg1) * H_NUM + h) * 64 + 2 * qc;
    #pragma unroll
    for (int dn = 0; dn < 8; dn++) {
        float2 r0v = make_float2(O[dn][0] * inv0, O[dn][1] * inv0);
        float2 r1v = make_float2(O[dn][2] * inv1, O[dn][3] * inv1);
        *(float2*)(o0 + 8 * dn) = r0v;
        *(float2*)(o1 + 8 * dn) = r1v;
    }
}

extern "C" void kernel_launch(void* const* d_in, const int* in_sizes, int n_in,
                              void* d_out, int out_size)
{
    const float* qkv = (const float*)d_in[0];
    const float* pb  = (const float*)d_in[1];
    float* out       = (float*)d_out;

    convert_kv_kernel<<<8192, 256>>>(qkv);   // 2^21 threads: full (b,s,kv,h,d4) space

    cudaFuncSetAttribute(fa_mma_kernel, cudaFuncAttributeMaxDynamicSharedMemorySize, DSMEM_BYTES);
    dim3 grid(S_LEN / MT, H_NUM, 2);
    fa_mma_kernel<<<grid, 256, DSMEM_BYTES>>>(qkv, pb, out);
}

// round 16
// speedup vs baseline: 1.0518x; 1.0410x over previous
#include <cuda_runtime.h>
#include <cuda_fp16.h>
#include <cstdint>

// FlashAttention via warp-level mma.sync (HMMA), sm_103 baseline target.
// B=2, S=2048, H=16, D=64, fp32 I/O.
// Round 16: R13 structure + batch-twin co-scheduling. pos_bias has no batch
//           dim; giving b=0/b=1 of the same (mi,h) adjacent blockIdx values
//           makes the second bias read hit L2 instead of DRAM (halves the
//           dominant DRAM stream and shortens the post-QK bias wait).

#define S_LEN 2048
#define H_NUM 16
#define MT    128
#define NT    64
#define SCALEF 0.125f

// dynamic smem offsets (bytes from 1024-aligned base); 128B rows, SW128
#define OFF_QHI  0            // 128 x 64 fp16 = 16KB
#define OFF_K0   16384        // stage 0: K (8KB)
#define OFF_K1   24576        // stage 1
#define OFF_VHI  32768        // 8KB
#define OFF_BIAS 40960        // 128 rows x 256B fp32 = 32KB (xor-16B swizzled)
#define DSMEM_BYTES (73728 + 1024)

// pre-converted K/V planes: [arr][b][h][s][d]; arr: 0=K 1=V
#define KV_PLANE (2u * H_NUM * S_LEN * 64u)
__device__ __half g_kv[2][2][H_NUM][S_LEN][64];

static __device__ __forceinline__ uint32_t swz(uint32_t o){ return o ^ ((o >> 3) & 0x70u); }

static __device__ __forceinline__ uint32_t smem_u32(const void* p){
    uint32_t a;
    asm("{ .reg .u64 t; cvta.to.shared.u64 t, %1; cvt.u32.u64 %0, t; }" : "=r"(a) : "l"(p));
    return a;
}

#define LDSM_X4(r, addr) \
    asm volatile("ldmatrix.sync.aligned.m8n8.x4.shared.b16 {%0,%1,%2,%3}, [%4];" \
        : "=r"((r)[0]), "=r"((r)[1]), "=r"((r)[2]), "=r"((r)[3]) : "r"(addr))

#define LDSM_X4T(r, addr) \
    asm volatile("ldmatrix.sync.aligned.m8n8.x4.trans.shared.b16 {%0,%1,%2,%3}, [%4];" \
        : "=r"((r)[0]), "=r"((r)[1]), "=r"((r)[2]), "=r"((r)[3]) : "r"(addr))

#define MMA(d, a, b0, b1) \
    asm volatile("mma.sync.aligned.m16n8k16.row.col.f32.f16.f16.f32 " \
        "{%0,%1,%2,%3},{%4,%5,%6,%7},{%8,%9},{%0,%1,%2,%3};" \
        : "+f"((d)[0]), "+f"((d)[1]), "+f"((d)[2]), "+f"((d)[3]) \
        : "r"((a)[0]), "r"((a)[1]), "r"((a)[2]), "r"((a)[3]), "r"(b0), "r"(b1))

#define CP16(smem, gmem) \
    asm volatile("cp.async.cg.shared.global [%0], [%1], 16;" :: "r"(smem), "l"(gmem))
#define CP_COMMIT() asm volatile("cp.async.commit_group;" ::: "memory")
#define CP_WAIT0()  asm volatile("cp.async.wait_group 0;"  ::: "memory")
#define CP_WAIT1()  asm volatile("cp.async.wait_group 1;"  ::: "memory")

static __device__ __forceinline__ uint32_t pk2h(float a, float b){
    uint32_t r;
    asm("cvt.rn.f16x2.f32 %0, %1, %2;" : "=r"(r) : "f"(b), "f"(a));
    return r;
}

// ---------------- pre-pass: K,V (fp32) -> fp16 planes ----------------
// Index space: 2^21 threads -> (b, s, kv, h, d4). Launch <<<8192, 256>>>.
__global__ void __launch_bounds__(256)
convert_kv_kernel(const float* __restrict__ qkv)
{
    const int idx = blockIdx.x * 256 + threadIdx.x;
    const int d4 = idx & 15;
    const int h  = (idx >> 4) & 15;
    const int kv = (idx >> 8) & 1;
    const int s  = (idx >> 9) & 2047;
    const int b  = idx >> 20;

    const float4 v = *(const float4*)(qkv
        + ((size_t)(b * 2048 + s) * 3 + 1 + kv) * 1024 + h * 64 + d4 * 4);
    uint32_t h0 = pk2h(v.x, v.y);
    uint32_t h1 = pk2h(v.z, v.w);
    *(uint2*)&g_kv[kv][b][h][s][d4 * 4] = make_uint2(h0, h1);
}

extern __shared__ char dynsm[];

__global__ void __launch_bounds__(256, 2)
fa_mma_kernel(const float* __restrict__ qkv, const float* __restrict__ pb,
              float* __restrict__ out)
{
    // blockIdx.x in [0,32): pair = x>>1 (tile row, big-first), b = x&1.
    // Batch twins of the same (mi,h) are adjacent -> co-resident -> the
    // second one's bias reads hit L2.
    const int mi  = 15 - (int)(blockIdx.x >> 1);
    const int b   = (int)(blockIdx.x & 1u);
    const int h   = blockIdx.y;
    const int tid = threadIdx.x;
    const int w   = tid >> 5;
    const int l   = tid & 31;
    const int qr  = l >> 2;
    const int qc  = l & 3;
    const int m0  = mi * MT;
    const int mg0 = m0 + w * 16 + qr;
    const int mg1 = mg0 + 8;
    const int wrow_max = m0 + w * 16 + 15;

    const uint32_t sbase = (smem_u32(dynsm) + 1023u) & ~1023u;
    const uint32_t sQ = sbase + OFF_QHI;
    const uint32_t sV = sbase + OFF_VHI;
    const uint32_t sB = sbase + OFF_BIAS;

    const float* qhd = qkv + (size_t)b * S_LEN * 3072 + (size_t)h * 64;
    const float* pbh = pb + (size_t)h * S_LEN * S_LEN;

    const int st_n = tid >> 4;
    const int st_g = tid & 15;

    // K/V cp.async mapping: thread -> row n (0..63), two 16B chunks
    const int kn  = tid >> 2;
    const int kc0 = (tid & 3) * 2;
    const uint32_t kd0 = swz((uint32_t)(kn * 128 + kc0 * 16));
    const uint32_t kd1 = swz((uint32_t)(kn * 128 + (kc0 + 1) * 16));
    const __half* kvbase = &g_kv[0][b][h][0][0];
    const size_t kv_row_off = (size_t)kn * 64 + kc0 * 8;

    // bias staging
    const float* bias_src0 = pbh + (size_t)(m0 + st_n) * S_LEN + st_g * 4;
    const uint32_t bias_dst = sB + (uint32_t)st_n * 256 + ((uint32_t)(st_g ^ (st_n & 15)) << 4);

    const int nt = 2 * (mi + 1);

    // ---- prologue: group {K(0)}, then group {bias(0), V(0)} ----
    {
        const __half* src = kvbase + kv_row_off;
        const uint32_t k0 = sbase + OFF_K0;
        CP16(k0 + kd0, src);                       CP16(k0 + kd1, src + 8);
        CP_COMMIT();   // K(0)
        #pragma unroll
        for (int r = 0; r < 8; r++)
            CP16(bias_dst + (uint32_t)r * 4096, bias_src0 + (size_t)r * 16 * S_LEN);
        CP16(sV + kd0, src + KV_PLANE);            CP16(sV + kd1, src + KV_PLANE + 8);
        CP_COMMIT();   // biasV(0)
    }

    // ---- stage Q (fp16, SW128) while tile-0 copies fly ----
    #pragma unroll
    for (int r = 0; r < 8; r++) {
        int idx = tid + r * 256;
        int m = idx >> 4, g = idx & 15;
        float4 v = *(const float4*)(qhd + (size_t)(m0 + m) * 3072 + g * 4);
        uint32_t o = swz((uint32_t)(m * 128 + g * 8));
        uint32_t h0 = pk2h(v.x, v.y), h1 = pk2h(v.z, v.w);
        asm volatile("st.shared.v2.u32 [%0], {%1,%2};" :: "r"(sQ + o), "r"(h0), "r"(h1));
    }

    float O[8][4];
    #pragma unroll
    for (int i = 0; i < 8; i++)
        #pragma unroll
        for (int j = 0; j < 4; j++) O[i][j] = 0.f;
    float lsum0 = 0.f, lsum1 = 0.f;

    const int r0loc = w * 16 + qr;
    const uint32_t bq = (uint32_t)(qc & 1) * 8;
    const int gq = qc >> 1;

    for (int t = 0; t < nt; t++) {
        const int n0 = t * NT;
        const bool active = (n0 <= wrow_max);
        const bool haveNext = (t + 1 < nt);
        const uint32_t sK  = sbase + ((t & 1) ? OFF_K1 : OFF_K0);
        const uint32_t sKn = sbase + ((t & 1) ? OFF_K0 : OFF_K1);

        // ---- wait K(t) (issued one phase ago; biasV(t) may still fly) ----
        CP_WAIT1();
        __syncthreads();

        // ---- S = Q K^T : fp16 x fp16 -> fp32 ----
        float S[8][4];
        if (active) {
            #pragma unroll
            for (int i = 0; i < 8; i++)
                #pragma unroll
                for (int j = 0; j < 4; j++) S[i][j] = 0.f;

            #pragma unroll
            for (int kt = 0; kt < 4; kt++) {
                uint32_t qh[4];
                uint32_t qoff = swz((uint32_t)((w * 16 + ((l >> 3) & 1) * 8 + (l & 7)) * 128
                                               + kt * 32 + (l >> 4) * 16));
                LDSM_X4(qh, sQ + qoff);
                #pragma unroll
                for (int np = 0; np < 4; np++) {
                    uint32_t kh[4];
                    uint32_t koff = swz((uint32_t)((np * 16 + ((l >> 4) & 1) * 8 + (l & 7)) * 128
                                                   + kt * 32 + ((l >> 3) & 1) * 16));
                    LDSM_X4(kh, sK + koff);
                    MMA(S[2*np],   qh, kh[0], kh[1]);
                    MMA(S[2*np+1], qh, kh[2], kh[3]);
                }
            }
        }

        // ---- wait biasV(t) (hidden under QK) ----
        CP_WAIT0();
        __syncthreads();     // K(t) reads done by all; bias+V visible

        // ---- issue K(t+1) into the freed alternate K buffer ----
        if (haveNext) {
            const __half* src = kvbase + (size_t)(n0 + NT) * 64 + kv_row_off;
            CP16(sKn + kd0, src);  CP16(sKn + kd1, src + 8);
        }
        CP_COMMIT();   // K(t+1) (empty group on last tile keeps counts aligned)

        // ---- epilogue + O += P V, interleaved per k16 group ----
        if (active) {
            const bool needmask = (n0 + 63 > m0 + w * 16);
            #pragma unroll
            for (int kp = 0; kp < 4; kp++) {
                uint32_t ph[4];
                #pragma unroll
                for (int jj = 0; jj < 2; jj++) {
                    const int j = 2 * kp + jj;
                    const int g16 = 2 * j + gq;
                    const uint32_t a0 = sB + (uint32_t)r0loc * 256
                                        + ((uint32_t)(g16 ^ (r0loc & 15)) << 4) + bq;
                    const uint32_t a1 = sB + (uint32_t)(r0loc + 8) * 256
                                        + ((uint32_t)(g16 ^ ((r0loc + 8) & 15)) << 4) + bq;
                    float b0x, b0y, b1x, b1y;
                    asm volatile("ld.shared.v2.f32 {%0,%1}, [%2];" : "=f"(b0x), "=f"(b0y) : "r"(a0));
                    asm volatile("ld.shared.v2.f32 {%0,%1}, [%2];" : "=f"(b1x), "=f"(b1y) : "r"(a1));
                    const int col = n0 + 8 * j + 2 * qc;
                    float p00 = __expf(fmaf(S[j][0], SCALEF, b0x));
                    float p01 = __expf(fmaf(S[j][1], SCALEF, b0y));
                    float p10 = __expf(fmaf(S[j][2], SCALEF, b1x));
                    float p11 = __expf(fmaf(S[j][3], SCALEF, b1y));
                    if (needmask) {
                        if (col     > mg0) p00 = 0.f;
                        if (col + 1 > mg0) p01 = 0.f;
                        if (col     > mg1) p10 = 0.f;
                        if (col + 1 > mg1) p11 = 0.f;
                    }
                    lsum0 += p00 + p01;
                    lsum1 += p10 + p11;
                    ph[jj*2]     = pk2h(p00, p01);
                    ph[jj*2 + 1] = pk2h(p10, p11);
                }
                #pragma unroll
                for (int dp = 0; dp < 4; dp++) {
                    uint32_t vh[4];
                    uint32_t voff = swz((uint32_t)((kp * 16 + ((l >> 3) & 1) * 8 + (l & 7)) * 128
                                                   + dp * 32 + ((l >> 4) & 1) * 16));
                    LDSM_X4T(vh, sV + voff);
                    MMA(O[2*dp],   ph, vh[0], vh[1]);
                    MMA(O[2*dp+1], ph, vh[2], vh[3]);
                }
            }
        }

        __syncthreads();   // bias/V reads done by all -> buffers free

        // ---- issue group {bias(t+1), V(t+1)} ----
        if (haveNext) {
            const int n1 = n0 + NT;
            const float* gsrc = bias_src0 + n1;
            #pragma unroll
            for (int r = 0; r < 8; r++)
                CP16(bias_dst + (uint32_t)r * 4096, gsrc + (size_t)r * 16 * S_LEN);
            const __half* src = kvbase + (size_t)n1 * 64 + kv_row_off;
            CP16(sV + kd0, src + KV_PLANE);  CP16(sV + kd1, src + KV_PLANE + 8);
        }
        CP_COMMIT();   // biasV(t+1)
    }

    // ---- normalize and store ----
    lsum0 += __shfl_xor_sync(0xffffffffu, lsum0, 1);
    lsum0 += __shfl_xor_sync(0xffffffffu, lsum0, 2);
    lsum1 += __shfl_xor_sync(0xffffffffu, lsum1, 1);
    lsum1 += __shfl_xor_sync(0xffffffffu, lsum1, 2);
    const float inv0 = 1.f / lsum0;
    const float inv1 = 1.f / lsum1;

    float* o0 = out + (((size_t)b * S_LEN + mg0) * H_NUM + h) * 64 + 2 * qc;
    float* o1 = out + (((size_t)b * S_LEN + mg1) * H_NUM + h) * 64 + 2 * qc;
    #pragma unroll
    for (int dn = 0; dn < 8; dn++) {
        float2 r0v = make_float2(O[dn][0] * inv0, O[dn][1] * inv0);
        float2 r1v = make_float2(O[dn][2] * inv1, O[dn][3] * inv1);
        *(float2*)(o0 + 8 * dn) = r0v;
        *(float2*)(o1 + 8 * dn) = r1v;
    }
}

extern "C" void kernel_launch(void* const* d_in, const int* in_sizes, int n_in,
                              void* d_out, int out_size)
{
    const float* qkv = (const float*)d_in[0];
    const float* pb  = (const float*)d_in[1];
    float* out       = (float*)d_out;

    convert_kv_kernel<<<8192, 256>>>(qkv);   // 2^21 threads: full (b,s,kv,h,d4) space

    cudaFuncSetAttribute(fa_mma_kernel, cudaFuncAttributeMaxDynamicSharedMemorySize, DSMEM_BYTES);
    dim3 grid(2 * (S_LEN / MT), H_NUM, 1);   // x: (tile-pair, batch) twins adjacent
    fa_mma_kernel<<<grid, 256, DSMEM_BYTES>>>(qkv, pb, out);
}